// round 3
// baseline (speedup 1.0000x reference)
#include <cuda_runtime.h>

#define BB 512
#define SS 1024
#define TT 48
#define LN64 4.1588830833596715f

__device__ float g_nll[BB];

// ---------------------------------------------------------------------------
// Fused forward + gold. One 48-thread block per batch. Thread j owns state j
// and E[:,j] = exp(trans[:,j]) in registers. State kept in probability domain
// q_j = exp(score_j - c); emissions folded in as pe = exp(emit)/64 computed at
// prefetch time (8 steps ahead), so the per-step critical path is only
// STS -> bar -> LDS -> FMA-tree -> mul.
// ---------------------------------------------------------------------------
__global__ void __launch_bounds__(48) crf_forward(
    const float* __restrict__ em,       // [B,S,T]
    const float* __restrict__ trans,    // [T,T]
    const float* __restrict__ startt,   // [T]
    const float* __restrict__ endt,     // [T]
    const int* __restrict__ tags,       // [B,S]
    const int* __restrict__ mask)       // [B,S] bool as int32
{
    __shared__ __align__(16) float p_sh[2 * 64];   // double buffer, 16B aligned
    __shared__ float red[TT], gred[TT];

    const int j = threadIdx.x;
    const int b = blockIdx.x;

    float E[TT];
#pragma unroll
    for (int i = 0; i < TT; i++) E[i] = __expf(__ldg(&trans[i * TT + j]));

    const float* emb = em + (size_t)b * SS * TT;
    const int* mk = mask + (size_t)b * SS;
    const int* tg = tags + (size_t)b * SS;

    const float e0 = emb[j];
    const int tg0 = tg[0];
    const int m0 = mk[0] ? 1 : 0;

    float q = __expf(startt[j] + e0);
    float c = 0.0f;
    int cnt = m0;                                  // total mask count
    float gold = (j == tg0) ? (startt[j] + e0) : 0.0f;
    int prev = tg0;

    const float inv64 = 0.015625f;
    float ee[8], pe[8];
    int mm[8], tgr[8];
#pragma unroll
    for (int k = 0; k < 8; k++) {
        int t = 1 + k;
        ee[k]  = emb[t * TT + j];
        pe[k]  = __expf(ee[k]) * inv64;
        mm[k]  = mk[t];
        tgr[k] = tg[t];
    }

    for (int t = 1; t < SS; t += 8) {
#pragma unroll
        for (int k = 0; k < 8; k++) {
            if (t + k < SS) {                       // uniform across block
                const int buf = (k + 1) & 1;        // static parity
                p_sh[buf * 64 + j] = q;
                __syncthreads();

                const float e_k  = ee[k];
                const float pe_k = pe[k];
                const int   m_k  = mm[k];
                const int   tgc  = tgr[k];

                // prefetch this slot for step t+8+k (hides DRAM + exp latency)
                const int tn = t + 8 + k;
                if (tn < SS) {
                    ee[k]  = emb[tn * TT + j];
                    pe[k]  = __expf(ee[k]) * inv64;
                    mm[k]  = mk[tn];
                    tgr[k] = tg[tn];
                }

                const float4* pv = (const float4*)(p_sh + buf * 64);
                float h[12], sh[12];
#pragma unroll
                for (int u = 0; u < 12; u++) {
                    float4 v = pv[u];
                    float x = v.x * E[4 * u + 0];
                    x = fmaf(v.y, E[4 * u + 1], x);
                    x = fmaf(v.z, E[4 * u + 2], x);
                    x = fmaf(v.w, E[4 * u + 3], x);
                    h[u] = x;
                    if (k == 3 || k == 7)           // static: renorm steps only
                        sh[u] = (v.x + v.y) + (v.z + v.w);
                }
                float acc = (((h[0] + h[1]) + (h[2] + h[3])) +
                             ((h[4] + h[5]) + (h[6] + h[7]))) +
                            ((h[8] + h[9]) + (h[10] + h[11]));

                float qn = acc * pe_k;
                q = m_k ? qn : q;

                if (k == 3 || k == 7) {             // renormalize every 4 steps
                    float ssum = (((sh[0] + sh[1]) + (sh[2] + sh[3])) +
                                  ((sh[4] + sh[5]) + (sh[6] + sh[7]))) +
                                 ((sh[8] + sh[9]) + (sh[10] + sh[11]));
                    q *= __fdividef(1.0f, ssum);
                    c += __logf(ssum);              // off critical path
                }

                // fused gold-path accumulation (off critical path)
                if (m_k) {
                    cnt++;
                    if (j == tgc) gold += e_k + __ldg(&trans[prev * TT + j]);
                }
                prev = tgc;
            }
        }
    }

    __syncthreads();
    red[j]  = q * __expf(endt[j]);
    gred[j] = gold;
    __syncthreads();
    if (j == 0) {
        float s = 0.0f, gg = 0.0f;
#pragma unroll
        for (int i = 0; i < TT; i++) { s += red[i]; gg += gred[i]; }
        float logZ = c + (float)(cnt - m0) * LN64 + __logf(s);
        int len = cnt - 1;                          // lengths = sum(mask) - 1
        gg += endt[tg[len]];
        g_nll[b] = logZ - gg;
    }
}

// ---------------------------------------------------------------------------
// Final mean over batches
// ---------------------------------------------------------------------------
__global__ void __launch_bounds__(512) crf_reduce(float* __restrict__ out)
{
    __shared__ float rs[512];
    const int tid = threadIdx.x;
    rs[tid] = g_nll[tid];
    __syncthreads();
    for (int off = 256; off > 0; off >>= 1) {
        if (tid < off) rs[tid] += rs[tid + off];
        __syncthreads();
    }
    if (tid == 0) out[0] = rs[0] / (float)BB;
}

extern "C" void kernel_launch(void* const* d_in, const int* in_sizes, int n_in,
                              void* d_out, int out_size)
{
    const float* em   = (const float*)d_in[0];
    const float* tr   = (const float*)d_in[1];
    const float* st   = (const float*)d_in[2];
    const float* en   = (const float*)d_in[3];
    const int*   tags = (const int*)d_in[4];
    const int*   mask = (const int*)d_in[5];
    float* out = (float*)d_out;

    crf_forward<<<BB, 48>>>(em, tr, st, en, tags, mask);
    crf_reduce<<<1, 512>>>(out);
}

// round 4
// speedup vs baseline: 1.9309x; 1.9309x over previous
#include <cuda_runtime.h>

#define BB 512
#define SS 1024
#define TT 48
#define LN64 4.1588830833596715f

__device__ float g_nll[BB];

// ---------------------------------------------------------------------------
// Fused forward + gold. One 48-thread block per batch. Thread j owns state j
// and E[:,j] = exp(trans[:,j]) in registers. State kept in probability domain
// q_j = exp(score_j - c). Emission LDGs run 8 steps ahead (raw, unconsumed ->
// true MLP=8, DRAM latency hidden); exp(emission)/64 is computed only at
// consumption time from an 8-step-old register (MUFU lat hidden by LDS+tree).
// ---------------------------------------------------------------------------
__global__ void __launch_bounds__(48) crf_forward(
    const float* __restrict__ em,       // [B,S,T]
    const float* __restrict__ trans,    // [T,T]
    const float* __restrict__ startt,   // [T]
    const float* __restrict__ endt,     // [T]
    const int* __restrict__ tags,       // [B,S]
    const int* __restrict__ mask)       // [B,S] bool as int32
{
    __shared__ __align__(16) float p_sh[2 * 64];   // double buffer, 16B aligned
    __shared__ float red[TT], gred[TT];

    const int j = threadIdx.x;
    const int b = blockIdx.x;

    float E[TT];
#pragma unroll
    for (int i = 0; i < TT; i++) E[i] = __expf(__ldg(&trans[i * TT + j]));

    const float* emb = em + (size_t)b * SS * TT;
    const int* mk = mask + (size_t)b * SS;
    const int* tg = tags + (size_t)b * SS;

    const float e0 = emb[j];
    const int tg0 = tg[0];
    const int m0 = mk[0] ? 1 : 0;

    float q = __expf(startt[j] + e0);
    float c = 0.0f;
    int cnt = m0;                                  // total mask count
    float gold = (j == tg0) ? (startt[j] + e0) : 0.0f;
    int prev = tg0;

    const float inv64 = 0.015625f;

    // raw prefetch buffers: loads only, no dependent math
    float ee[8];
    int mm[8], tgr[8];
#pragma unroll
    for (int k = 0; k < 8; k++) {
        int t = 1 + k;
        ee[k]  = emb[t * TT + j];
        mm[k]  = mk[t];
        tgr[k] = tg[t];
    }

    for (int t = 1; t < SS; t += 8) {
#pragma unroll
        for (int k = 0; k < 8; k++) {
            if (t + k < SS) {                       // uniform across block
                const int buf = (k + 1) & 1;        // static parity
                p_sh[buf * 64 + j] = q;

                // consume 8-step-old registers; exp issued before the barrier
                const float e_k  = ee[k];
                const float pe_k = __expf(e_k) * inv64;
                const int   m_k  = mm[k];
                const int   tgc  = tgr[k];

                __syncthreads();

                // prefetch (load ONLY) this slot for step t+8+k
                const int tn = t + 8 + k;
                if (tn < SS) {
                    ee[k]  = emb[tn * TT + j];
                    mm[k]  = mk[tn];
                    tgr[k] = tg[tn];
                }

                const float4* pv = (const float4*)(p_sh + buf * 64);
                float h[12], sh[12];
#pragma unroll
                for (int u = 0; u < 12; u++) {
                    float4 v = pv[u];
                    float x = v.x * E[4 * u + 0];
                    x = fmaf(v.y, E[4 * u + 1], x);
                    x = fmaf(v.z, E[4 * u + 2], x);
                    x = fmaf(v.w, E[4 * u + 3], x);
                    h[u] = x;
                    if (k == 3 || k == 7)           // static: renorm steps only
                        sh[u] = (v.x + v.y) + (v.z + v.w);
                }
                float acc = (((h[0] + h[1]) + (h[2] + h[3])) +
                             ((h[4] + h[5]) + (h[6] + h[7]))) +
                            ((h[8] + h[9]) + (h[10] + h[11]));

                float qn = acc * pe_k;
                q = m_k ? qn : q;

                if (k == 3 || k == 7) {             // renormalize every 4 steps
                    float ssum = (((sh[0] + sh[1]) + (sh[2] + sh[3])) +
                                  ((sh[4] + sh[5]) + (sh[6] + sh[7]))) +
                                 ((sh[8] + sh[9]) + (sh[10] + sh[11]));
                    q *= __fdividef(1.0f, ssum);
                    c += __logf(ssum);              // off critical path
                }

                // fused gold-path accumulation (off critical path)
                if (m_k) {
                    cnt++;
                    if (j == tgc) gold += e_k + __ldg(&trans[prev * TT + j]);
                }
                prev = tgc;
            }
        }
    }

    __syncthreads();
    red[j]  = q * __expf(endt[j]);
    gred[j] = gold;
    __syncthreads();
    if (j == 0) {
        float s = 0.0f, gg = 0.0f;
#pragma unroll
        for (int i = 0; i < TT; i++) { s += red[i]; gg += gred[i]; }
        float logZ = c + (float)(cnt - m0) * LN64 + __logf(s);
        int len = cnt - 1;                          // lengths = sum(mask) - 1
        gg += endt[tg[len]];
        g_nll[b] = logZ - gg;
    }
}

// ---------------------------------------------------------------------------
// Final mean over batches
// ---------------------------------------------------------------------------
__global__ void __launch_bounds__(512) crf_reduce(float* __restrict__ out)
{
    __shared__ float rs[512];
    const int tid = threadIdx.x;
    rs[tid] = g_nll[tid];
    __syncthreads();
    for (int off = 256; off > 0; off >>= 1) {
        if (tid < off) rs[tid] += rs[tid + off];
        __syncthreads();
    }
    if (tid == 0) out[0] = rs[0] / (float)BB;
}

extern "C" void kernel_launch(void* const* d_in, const int* in_sizes, int n_in,
                              void* d_out, int out_size)
{
    const float* em   = (const float*)d_in[0];
    const float* tr   = (const float*)d_in[1];
    const float* st   = (const float*)d_in[2];
    const float* en   = (const float*)d_in[3];
    const int*   tags = (const int*)d_in[4];
    const int*   mask = (const int*)d_in[5];
    float* out = (float*)d_out;

    crf_forward<<<BB, 48>>>(em, tr, st, en, tags, mask);
    crf_reduce<<<1, 512>>>(out);
}